// round 12
// baseline (speedup 1.0000x reference)
#include <cuda_runtime.h>
#include <cstdint>

#define BATCH 512
#define CHANNELS 256
#define KXS 6
#define KZ 22
#define HO 17
#define OUT_PER_B 289
#define N_OUT (BATCH*OUT_PER_B)

#define SPLITS 8
#define CH_PER_SPLIT (CHANNELS/SPLITS)   // 32
#define CH_CHUNK 8                  // 4 pairs per chunk
#define PAIRS_C 4
#define ITERS (CH_PER_SPLIT/CH_CHUNK)    // 4
#define THREADS 136                 // 17 rows x (4 pairs x 2 ky-halves)
#define LANES 8

#define ZPAIR_FLOATS (KZ*KZ*2)      // 968
#define ZROW_PAIRF 44
#define XPAIR_FLOATS (KXS*KXS*2)    // 72
#define ZBUF_FLOATS (PAIRS_C*ZPAIR_FLOATS)   // 3872
#define XBUF_FLOATS (PAIRS_C*XPAIR_FLOATS)   // 288
#define BUF_FLOATS (ZBUF_FLOATS + XBUF_FLOATS)   // 4160
#define SMEM_BYTES (2*BUF_FLOATS*4)              // 33280

#define Z_UNITS (PAIRS_C*121)       // 484
#define X_UNITS (PAIRS_C*9)         // 36
#define PFK 4

#define ZCHUNK_F4 (CH_CHUNK*KZ*KZ/4)    // 968
#define XCHUNK_F4 (CH_CHUNK*KXS*KXS/4)  // 72

typedef unsigned long long ull;

__device__ float g_partial[SPLITS * N_OUT];
__device__ int   g_count[BATCH];    // zero-init; reset by last CTA each use

__device__ __forceinline__ void fma2(ull& d, ull a, ull b) {
    asm("fma.rn.f32x2 %0, %1, %2, %0;" : "+l"(d) : "l"(a), "l"(b));
}
__device__ __forceinline__ void unpack2(ull v, float& lo, float& hi) {
    asm("mov.b64 {%0, %1}, %2;" : "=f"(lo), "=f"(hi) : "l"(v));
}

__global__ __launch_bounds__(THREADS, 5)
void corr_main_kernel(const float* __restrict__ x, const float* __restrict__ z,
                      float* __restrict__ out)
{
    extern __shared__ float smem[];   // ping-pong buffers
    __shared__ int s_last;

    const int tid  = threadIdx.x;
    const int i    = tid % HO;        // output row
    const int lane = tid / HO;        // 0..7
    const int p    = lane >> 1;       // pair 0..3
    const int h    = lane & 1;        // ky half
    const int b     = blockIdx.x >> 3;
    const int split = blockIdx.x & 7;
    const int cbase = split * CH_PER_SPLIT;

    // chunk-invariant staging map
    int zsrc_off[PFK], zdst_off[PFK];
    #pragma unroll
    for (int k = 0; k < PFK; k++) {
        int u = tid + k * THREADS;
        if (u < Z_UNITS) {
            int pu = u / 121;
            int w4 = u - pu * 121;
            zsrc_off[k] = 2 * pu * 121 + w4;
            zdst_off[k] = pu * ZPAIR_FLOATS + 8 * w4;
        } else { zsrc_off[k] = -1; zdst_off[k] = 0; }
    }
    int xsrc_off = -1, xdst_off = 0;
    if (tid < X_UNITS) {
        int pu = tid / 9, w4 = tid - pu * 9;
        xsrc_off = 2 * pu * 9 + w4;
        xdst_off = pu * XPAIR_FLOATS + 8 * w4;
    }

    const float4* zg = reinterpret_cast<const float4*>(
        z + ((size_t)b * CHANNELS + cbase) * (KZ * KZ));
    const float4* xg = reinterpret_cast<const float4*>(
        x + ((size_t)b * CHANNELS + cbase) * (KXS * KXS));

    // ---- stage chunk 0 into buf0 ----
    {
        float* zb0 = smem;
        float* xb0 = smem + ZBUF_FLOATS;
        #pragma unroll
        for (int k = 0; k < PFK; k++)
            if (zsrc_off[k] >= 0) {
                float4 a = zg[zsrc_off[k]];
                float4 c = zg[zsrc_off[k] + 121];
                float4* d4 = reinterpret_cast<float4*>(zb0 + zdst_off[k]);
                d4[0] = make_float4(a.x, c.x, a.y, c.y);
                d4[1] = make_float4(a.z, c.z, a.w, c.w);
            }
        if (xsrc_off >= 0) {
            float4 a = xg[xsrc_off];
            float4 c = xg[xsrc_off + 9];
            float4* d4 = reinterpret_cast<float4*>(xb0 + xdst_off);
            d4[0] = make_float4(a.x, c.x, a.y, c.y);
            d4[1] = make_float4(a.z, c.z, a.w, c.w);
        }
    }
    __syncthreads();

    ull acc[HO];
    #pragma unroll
    for (int j = 0; j < HO; j++) acc[j] = 0ull;

    #pragma unroll 1
    for (int it = 0; it < ITERS; ++it) {
        // ---- stage chunk it+1 into the other buffer ----
        if (it + 1 < ITERS) {
            const float4* zpn = zg + (size_t)(it + 1) * ZCHUNK_F4;
            const float4* xpn = xg + (size_t)(it + 1) * XCHUNK_F4;
            float* zbn = smem + ((it + 1) & 1) * BUF_FLOATS;
            float* xbn = zbn + ZBUF_FLOATS;
            #pragma unroll
            for (int k = 0; k < PFK; k++)
                if (zsrc_off[k] >= 0) {
                    float4 a = zpn[zsrc_off[k]];
                    float4 c = zpn[zsrc_off[k] + 121];
                    float4* d4 = reinterpret_cast<float4*>(zbn + zdst_off[k]);
                    d4[0] = make_float4(a.x, c.x, a.y, c.y);
                    d4[1] = make_float4(a.z, c.z, a.w, c.w);
                }
            if (xsrc_off >= 0) {
                float4 a = xpn[xsrc_off];
                float4 c = xpn[xsrc_off + 9];
                float4* d4 = reinterpret_cast<float4*>(xbn + xdst_off);
                d4[0] = make_float4(a.x, c.x, a.y, c.y);
                d4[1] = make_float4(a.z, c.z, a.w, c.w);
            }
        }

        // ---- compute from buf[it&1] ----
        {
            const float* zbuf = smem + (it & 1) * BUF_FLOATS;
            const float* xbuf = zbuf + ZBUF_FLOATS;
            const float* zc = zbuf + p * ZPAIR_FLOATS;
            const float* xcp = xbuf + p * XPAIR_FLOATS;
            #pragma unroll
            for (int kk = 0; kk < 3; kk++) {
                const int ky = 3 * h + kk;
                const ull* zrow = reinterpret_cast<const ull*>(
                    zc + (i + ky) * ZROW_PAIRF);
                ull xx[6];
                {
                    const ulonglong2* x2 = reinterpret_cast<const ulonglong2*>(
                        xcp + ky * (KXS * 2));
                    ulonglong2 t0 = x2[0], t1 = x2[1], t2 = x2[2];
                    xx[0] = t0.x; xx[1] = t0.y;
                    xx[2] = t1.x; xx[3] = t1.y;
                    xx[4] = t2.x; xx[5] = t2.y;
                }
                { // half A: positions 0..12
                    ull zp[13];
                    const ulonglong2* z2 = reinterpret_cast<const ulonglong2*>(zrow);
                    #pragma unroll
                    for (int q = 0; q < 6; q++) {
                        ulonglong2 t = z2[q];
                        zp[2*q] = t.x; zp[2*q+1] = t.y;
                    }
                    zp[12] = zrow[12];
                    #pragma unroll
                    for (int kx = 0; kx < KXS; kx++)
                        #pragma unroll
                        for (int j = 0; j <= 12 - kx; j++)
                            fma2(acc[j], zp[j + kx], xx[kx]);
                }
                { // half B: positions 13..21
                    ull zq[9];
                    zq[0] = zrow[13];
                    const ulonglong2* z2 = reinterpret_cast<const ulonglong2*>(zrow + 14);
                    #pragma unroll
                    for (int q = 0; q < 4; q++) {
                        ulonglong2 t = z2[q];
                        zq[1+2*q] = t.x; zq[2+2*q] = t.y;
                    }
                    #pragma unroll
                    for (int kx = 0; kx < KXS; kx++)
                        #pragma unroll
                        for (int j = 13 - kx; j < HO; j++)
                            fma2(acc[j], zq[j + kx - 13], xx[kx]);
                }
            }
        }
        __syncthreads();
    }

    // ---- fold pair lanes, reduce 8 lanes via smem scratch ----
    float* scratch = smem;   // 8*289 floats
    #pragma unroll
    for (int j = 0; j < HO; j++) {
        float lo, hi;
        unpack2(acc[j], lo, hi);
        scratch[lane * OUT_PER_B + i * HO + j] = lo + hi;
    }
    __syncthreads();

    float* gp = &g_partial[(size_t)split * N_OUT + (size_t)b * OUT_PER_B];
    for (int o = tid; o < OUT_PER_B; o += THREADS) {
        float s = 0.f;
        #pragma unroll
        for (int l = 0; l < LANES; l++)
            s += scratch[l * OUT_PER_B + o];
        gp[o] = s;
    }

    // ---- last CTA of this batch performs the final cross-split reduce ----
    __threadfence();
    if (tid == 0) {
        int v = atomicAdd(&g_count[b], 1);
        if (v == SPLITS - 1) {
            g_count[b] = 0;          // reset for next graph replay
            s_last = 1;
        } else {
            s_last = 0;
        }
    }
    __syncthreads();

    if (s_last) {
        __threadfence();             // observe all splits' g_partial
        float* ob = out + (size_t)b * OUT_PER_B;
        const float* gpb = &g_partial[(size_t)b * OUT_PER_B];
        for (int o = tid; o < OUT_PER_B; o += THREADS) {
            float s = 0.f;
            #pragma unroll
            for (int sp = 0; sp < SPLITS; sp++)
                s += gpb[(size_t)sp * N_OUT + o];
            ob[o] = s;
        }
    }
}

extern "C" void kernel_launch(void* const* d_in, const int* in_sizes, int n_in,
                              void* d_out, int out_size)
{
    const float* a = (const float*)d_in[0];
    const float* bptr = (const float*)d_in[1];
    const float* x;
    const float* z;
    if (in_sizes[0] == BATCH * CHANNELS * KXS * KXS) { x = a;    z = bptr; }
    else                                             { x = bptr; z = a;   }

    float* out = (float*)d_out;

    cudaFuncSetAttribute(corr_main_kernel,
                         cudaFuncAttributeMaxDynamicSharedMemorySize, SMEM_BYTES);
    corr_main_kernel<<<BATCH * SPLITS, THREADS, SMEM_BYTES>>>(x, z, out);
}

// round 13
// speedup vs baseline: 1.0319x; 1.0319x over previous
#include <cuda_runtime.h>
#include <cstdint>

#define BATCH 512
#define CHANNELS 256
#define KXS 6
#define KZ 22
#define HO 17
#define OUT_PER_B 289
#define N_OUT (BATCH*OUT_PER_B)

#define SPLITS 8
#define CH_PER_SPLIT (CHANNELS/SPLITS)   // 32
#define CH_CHUNK 8                  // 4 pairs per chunk
#define PAIRS_C 4
#define ITERS (CH_PER_SPLIT/CH_CHUNK)    // 4
#define THREADS 136                 // 17 rows x (4 pairs x 2 ky-halves)
#define LANES 8

#define ZPAIR_FLOATS (KZ*KZ*2)      // 968
#define ZROW_PAIRF 44
#define XPAIR_FLOATS (KXS*KXS*2)    // 72
#define ZBUF_FLOATS (PAIRS_C*ZPAIR_FLOATS)   // 3872
#define XBUF_FLOATS (PAIRS_C*XPAIR_FLOATS)   // 288
#define BUF_FLOATS (ZBUF_FLOATS + XBUF_FLOATS)   // 4160
#define SMEM_BYTES (2*BUF_FLOATS*4)              // 33280

// staging in 16B "half-units": one dst float4 per half-unit
#define Z_HUNITS (PAIRS_C*121*2)    // 968
#define X_HUNITS (PAIRS_C*9*2)      // 72
#define PFK 8                       // 968 = 7*136 + 16

// per-chunk slab strides in float2 units
#define ZCHUNK_F2 (CH_CHUNK*KZ*KZ/2)    // 1936
#define XCHUNK_F2 (CH_CHUNK*KXS*KXS/2)  // 144

typedef unsigned long long ull;

__device__ float g_partial[SPLITS * N_OUT];

__device__ __forceinline__ void fma2(ull& d, ull a, ull b) {
    asm("fma.rn.f32x2 %0, %1, %2, %0;" : "+l"(d) : "l"(a), "l"(b));
}
__device__ __forceinline__ void unpack2(ull v, float& lo, float& hi) {
    asm("mov.b64 {%0, %1}, %2;" : "=f"(lo), "=f"(hi) : "l"(v));
}

__global__ __launch_bounds__(THREADS, 6)
void corr_main_kernel(const float* __restrict__ x, const float* __restrict__ z)
{
    extern __shared__ float smem[];   // ping-pong buffers

    const int tid  = threadIdx.x;
    const int i    = tid % HO;        // output row
    const int lane = tid / HO;        // 0..7
    const int p    = lane >> 1;       // pair 0..3
    const int h    = lane & 1;        // ky half
    const int b     = blockIdx.x >> 3;
    const int split = blockIdx.x & 7;
    const int cbase = split * CH_PER_SPLIT;

    // chunk-invariant staging map (half-unit = one 16B dst block)
    // src offsets in float2 units relative to chunk base
    int zs_a[PFK], zs_dst[PFK];
    #pragma unroll
    for (int k = 0; k < PFK; k++) {
        int hu = tid + k * THREADS;
        if (hu < Z_HUNITS) {
            int u    = hu >> 1;
            int half = hu & 1;
            int pu = u / 121;
            int w4 = u - pu * 121;
            zs_a[k]   = pu * 484 + 2 * w4 + half;          // ch 2pu float2 idx; ch 2pu+1 = +242
            zs_dst[k] = pu * ZPAIR_FLOATS + 8 * w4 + 4 * half;
        } else { zs_a[k] = -1; zs_dst[k] = 0; }
    }
    int xs_a = -1, xs_dst = 0;
    if (tid < X_HUNITS) {
        int u = tid >> 1, half = tid & 1;
        int pu = u / 9, w4 = u - pu * 9;
        xs_a   = pu * 36 + 2 * w4 + half;                  // ch 2pu+1 = +18
        xs_dst = pu * XPAIR_FLOATS + 8 * w4 + 4 * half;
    }

    const float2* zg2 = reinterpret_cast<const float2*>(
        z + ((size_t)b * CHANNELS + cbase) * (KZ * KZ));
    const float2* xg2 = reinterpret_cast<const float2*>(
        x + ((size_t)b * CHANNELS + cbase) * (KXS * KXS));

    // ---- stage chunk 0 into buf0 ----
    {
        float* zb0 = smem;
        float* xb0 = smem + ZBUF_FLOATS;
        #pragma unroll
        for (int k = 0; k < PFK; k++)
            if (zs_a[k] >= 0) {
                float2 a = zg2[zs_a[k]];
                float2 c = zg2[zs_a[k] + 242];
                *reinterpret_cast<float4*>(zb0 + zs_dst[k]) =
                    make_float4(a.x, c.x, a.y, c.y);
            }
        if (xs_a >= 0) {
            float2 a = xg2[xs_a];
            float2 c = xg2[xs_a + 18];
            *reinterpret_cast<float4*>(xb0 + xs_dst) =
                make_float4(a.x, c.x, a.y, c.y);
        }
    }
    __syncthreads();

    ull acc[HO];
    #pragma unroll
    for (int j = 0; j < HO; j++) acc[j] = 0ull;

    #pragma unroll 1
    for (int it = 0; it < ITERS; ++it) {
        // ---- stage chunk it+1 into the other buffer ----
        if (it + 1 < ITERS) {
            const float2* zpn = zg2 + (size_t)(it + 1) * ZCHUNK_F2;
            const float2* xpn = xg2 + (size_t)(it + 1) * XCHUNK_F2;
            float* zbn = smem + ((it + 1) & 1) * BUF_FLOATS;
            float* xbn = zbn + ZBUF_FLOATS;
            #pragma unroll
            for (int k = 0; k < PFK; k++)
                if (zs_a[k] >= 0) {
                    float2 a = zpn[zs_a[k]];
                    float2 c = zpn[zs_a[k] + 242];
                    *reinterpret_cast<float4*>(zbn + zs_dst[k]) =
                        make_float4(a.x, c.x, a.y, c.y);
                }
            if (xs_a >= 0) {
                float2 a = xpn[xs_a];
                float2 c = xpn[xs_a + 18];
                *reinterpret_cast<float4*>(xbn + xs_dst) =
                    make_float4(a.x, c.x, a.y, c.y);
            }
        }

        // ---- compute from buf[it&1] ----
        {
            const float* zbuf = smem + (it & 1) * BUF_FLOATS;
            const float* xbuf = zbuf + ZBUF_FLOATS;
            const float* zc = zbuf + p * ZPAIR_FLOATS;
            const float* xcp = xbuf + p * XPAIR_FLOATS;
            #pragma unroll
            for (int kk = 0; kk < 3; kk++) {
                const int ky = 3 * h + kk;
                const ull* zrow = reinterpret_cast<const ull*>(
                    zc + (i + ky) * ZROW_PAIRF);
                ull xx[6];
                {
                    const ulonglong2* x2 = reinterpret_cast<const ulonglong2*>(
                        xcp + ky * (KXS * 2));
                    ulonglong2 t0 = x2[0], t1 = x2[1], t2 = x2[2];
                    xx[0] = t0.x; xx[1] = t0.y;
                    xx[2] = t1.x; xx[3] = t1.y;
                    xx[4] = t2.x; xx[5] = t2.y;
                }
                ull z13;
                { // half A: positions 0..12 (load 0..13 as 7 LDS.128)
                    ull zp[14];
                    const ulonglong2* z2 = reinterpret_cast<const ulonglong2*>(zrow);
                    #pragma unroll
                    for (int q = 0; q < 7; q++) {
                        ulonglong2 t = z2[q];
                        zp[2*q] = t.x; zp[2*q+1] = t.y;
                    }
                    z13 = zp[13];
                    #pragma unroll
                    for (int kx = 0; kx < KXS; kx++)
                        #pragma unroll
                        for (int j = 0; j <= 12 - kx; j++)
                            fma2(acc[j], zp[j + kx], xx[kx]);
                }
                { // half B: positions 13..21
                    ull zq[9];
                    zq[0] = z13;
                    const ulonglong2* z2 = reinterpret_cast<const ulonglong2*>(zrow + 14);
                    #pragma unroll
                    for (int q = 0; q < 4; q++) {
                        ulonglong2 t = z2[q];
                        zq[1+2*q] = t.x; zq[2+2*q] = t.y;
                    }
                    #pragma unroll
                    for (int kx = 0; kx < KXS; kx++)
                        #pragma unroll
                        for (int j = 13 - kx; j < HO; j++)
                            fma2(acc[j], zq[j + kx - 13], xx[kx]);
                }
            }
        }
        __syncthreads();
    }

    // ---- fold pair lanes, reduce 8 lanes via smem scratch ----
    float* scratch = smem;   // 8*289 floats
    #pragma unroll
    for (int j = 0; j < HO; j++) {
        float lo, hi;
        unpack2(acc[j], lo, hi);
        scratch[lane * OUT_PER_B + i * HO + j] = lo + hi;
    }
    __syncthreads();

    for (int o = tid; o < OUT_PER_B; o += THREADS) {
        float s = 0.f;
        #pragma unroll
        for (int l = 0; l < LANES; l++)
            s += scratch[l * OUT_PER_B + o];
        g_partial[((size_t)split * BATCH + b) * OUT_PER_B + o] = s;
    }
}

__global__ void corr_reduce_kernel(float* __restrict__ out)
{
    int idx = blockIdx.x * blockDim.x + threadIdx.x;
    if (idx < N_OUT) {
        float s = 0.f;
        #pragma unroll
        for (int sp = 0; sp < SPLITS; sp++)
            s += g_partial[(size_t)sp * N_OUT + idx];
        out[idx] = s;
    }
}

extern "C" void kernel_launch(void* const* d_in, const int* in_sizes, int n_in,
                              void* d_out, int out_size)
{
    const float* a = (const float*)d_in[0];
    const float* bptr = (const float*)d_in[1];
    const float* x;
    const float* z;
    if (in_sizes[0] == BATCH * CHANNELS * KXS * KXS) { x = a;    z = bptr; }
    else                                             { x = bptr; z = a;   }

    float* out = (float*)d_out;

    cudaFuncSetAttribute(corr_main_kernel,
                         cudaFuncAttributeMaxDynamicSharedMemorySize, SMEM_BYTES);
    corr_main_kernel<<<BATCH * SPLITS, THREADS, SMEM_BYTES>>>(x, z);
    corr_reduce_kernel<<<(N_OUT + 255) / 256, 256>>>(out);
}